// round 17
// baseline (speedup 1.0000x reference)
#include <cuda_runtime.h>
#include <cuda_bf16.h>

#define N_NODES 100000
#define N_EDGES 600000
#define F 128
#define SCAN_B 512
#define NB_SCAN ((N_NODES + SCAN_B - 1) / SCAN_B)   // 196
#define ZERO_BLOCKS 391                              // 391*256 >= N_NODES

// ---------------- scratch (device globals: proven-safe classes) ---------------
__device__ int   g_deg[N_NODES];
__device__ int   g_cur[N_NODES];
__device__ int   g_off[N_NODES + 1];
__device__ int   g_srcs[N_EDGES];
__device__ int   g_bsum[256];
__device__ float g_agg[(size_t)N_NODES * F];
__device__ float g_h1 [(size_t)N_NODES * F];
// packed bf16 planes of the 5 weights: [w][ck][row][16 uints] (hi and lo)
__device__ unsigned g_wpkh[5 * 4 * 128 * 16];
__device__ unsigned g_wpkl[5 * 4 * 128 * 16];

// ---------------- helpers ------------------------------------------------------
#define SPLITPACK(vx, vy, hp_, lp_) { \
    __nv_bfloat16 h0_ = __float2bfloat16_rn(vx); \
    __nv_bfloat16 h1_ = __float2bfloat16_rn(vy); \
    __nv_bfloat16 l0_ = __float2bfloat16_rn((vx) - __bfloat162float(h0_)); \
    __nv_bfloat16 l1_ = __float2bfloat16_rn((vy) - __bfloat162float(h1_)); \
    hp_ = (unsigned)__bfloat16_as_ushort(h0_) | ((unsigned)__bfloat16_as_ushort(h1_) << 16); \
    lp_ = (unsigned)__bfloat16_as_ushort(l0_) | ((unsigned)__bfloat16_as_ushort(l1_) << 16); }

// ---------------- prep: zero g_deg + pack weights (fused) ---------------------
__global__ void prep_kernel(const float* __restrict__ w1l, const float* __restrict__ w1r,
                            const float* __restrict__ w2l, const float* __restrict__ w2r,
                            const float* __restrict__ wdec) {
    int b = blockIdx.x;
    if (b < ZERO_BLOCKS) {
        int i = b * 256 + threadIdx.x;
        if (i < N_NODES) g_deg[i] = 0;
    } else {
        int t = (b - ZERO_BLOCKS) * 256 + threadIdx.x;
        if (t >= 5 * 128 * 32) return;
        int w = t >> 12, rem = t & 4095;
        int row = rem >> 5, k4 = rem & 31;
        const float* wp;
        if      (w == 0) wp = w1l;
        else if (w == 1) wp = w1r;
        else if (w == 2) wp = w2l;
        else if (w == 3) wp = w2r;
        else             wp = wdec;
        float4 v = reinterpret_cast<const float4*>(wp)[row * 32 + k4];
        unsigned hp0, lp0, hp1, lp1;
        SPLITPACK(v.x, v.y, hp0, lp0);
        SPLITPACK(v.z, v.w, hp1, lp1);
        size_t u2 = ((size_t)((w * 4 + (k4 >> 3)) * 128 + row) * 8 + (k4 & 7));
        reinterpret_cast<uint2*>(g_wpkh)[u2] = make_uint2(hp0, hp1);
        reinterpret_cast<uint2*>(g_wpkl)[u2] = make_uint2(lp0, lp1);
    }
}

// ---------------- CSR build ---------------------------------------------------
__global__ void hist_kernel(const int* __restrict__ edges) {
    int i = blockIdx.x * blockDim.x + threadIdx.x;
    if (i < N_EDGES) {
        unsigned d = (unsigned)edges[N_EDGES + i];
        if (d < N_NODES) atomicAdd(&g_deg[d], 1);
    }
}

__global__ void scan1_kernel() {
    __shared__ int s[SCAN_B];
    int i = blockIdx.x * SCAN_B + threadIdx.x;
    int v = (i < N_NODES) ? g_deg[i] : 0;
    s[threadIdx.x] = v;
    __syncthreads();
    for (int off = 1; off < SCAN_B; off <<= 1) {
        int t = (threadIdx.x >= off) ? s[threadIdx.x - off] : 0;
        __syncthreads();
        s[threadIdx.x] += t;
        __syncthreads();
    }
    if (i < N_NODES) g_off[i] = s[threadIdx.x] - v;
    if (threadIdx.x == SCAN_B - 1) g_bsum[blockIdx.x] = s[SCAN_B - 1];
}

__global__ void scan2_kernel() {
    __shared__ int s[256];
    int t = threadIdx.x;
    int v = (t < NB_SCAN) ? g_bsum[t] : 0;
    s[t] = v;
    __syncthreads();
    for (int off = 1; off < 256; off <<= 1) {
        int u = (t >= off) ? s[t - off] : 0;
        __syncthreads();
        s[t] += u;
        __syncthreads();
    }
    if (t < NB_SCAN) g_bsum[t] = s[t] - v;
    if (t == 255) g_off[N_NODES] = s[255];
}

__global__ void scan3_kernel() {
    int i = blockIdx.x * SCAN_B + threadIdx.x;
    if (i < N_NODES) {
        int o = g_off[i] + g_bsum[blockIdx.x];
        g_off[i] = o;
        g_cur[i] = o;          // absolute write cursor for fill
    }
}

__global__ void fill_kernel(const int* __restrict__ edges) {
    int i = blockIdx.x * blockDim.x + threadIdx.x;
    if (i < N_EDGES) {
        unsigned s = (unsigned)edges[i];
        unsigned d = (unsigned)edges[N_EDGES + i];
        if (s < N_NODES && d < N_NODES) {
            int p = atomicAdd(&g_cur[d], 1);
            g_srcs[p] = (int)s;
        }
    }
}

// ---------------- mma.sync bf16-split GEMM (64-row tile + reg prefetch) -------
// smem: Ah[0,5120) Al[5120,10240) Wh[10240,20480) Wl[20480,30720); stride 80B.
#define MMAS(c0, c1, c2, c3, a0, a1, a2, a3, b0, b1) \
    asm volatile("mma.sync.aligned.m16n8k16.row.col.f32.bf16.bf16.f32 " \
        "{%0,%1,%2,%3}, {%4,%5,%6,%7}, {%8,%9}, {%0,%1,%2,%3};" \
        : "+f"(c0), "+f"(c1), "+f"(c2), "+f"(c3) \
        : "r"(a0), "r"(a1), "r"(a2), "r"(a3), "r"(b0), "r"(b1))

#define DACC_P(P, mt, nt) \
    float P##mt##nt##_0 = 0.f, P##mt##nt##_1 = 0.f, P##mt##nt##_2 = 0.f, P##mt##nt##_3 = 0.f

#define LDA(mt) \
    unsigned AH##mt##_0, AH##mt##_1, AH##mt##_2, AH##mt##_3; \
    unsigned AL##mt##_0, AL##mt##_1, AL##mt##_2, AL##mt##_3; \
    { unsigned o_ = aBase + (unsigned)(mt * 16 * 80) + kb; \
      AH##mt##_0 = *reinterpret_cast<const unsigned*>(sm + o_); \
      AH##mt##_1 = *reinterpret_cast<const unsigned*>(sm + o_ + 640); \
      AH##mt##_2 = *reinterpret_cast<const unsigned*>(sm + o_ + 16); \
      AH##mt##_3 = *reinterpret_cast<const unsigned*>(sm + o_ + 656); \
      AL##mt##_0 = *reinterpret_cast<const unsigned*>(sm + o_ + 5120); \
      AL##mt##_1 = *reinterpret_cast<const unsigned*>(sm + o_ + 5760); \
      AL##mt##_2 = *reinterpret_cast<const unsigned*>(sm + o_ + 5136); \
      AL##mt##_3 = *reinterpret_cast<const unsigned*>(sm + o_ + 5776); }

#define LDW(nt) \
    unsigned WH##nt##_0, WH##nt##_1, WL##nt##_0, WL##nt##_1; \
    { unsigned o_ = wBase + (unsigned)(nt * 8 * 80) + kb; \
      WH##nt##_0 = *reinterpret_cast<const unsigned*>(sm + o_); \
      WH##nt##_1 = *reinterpret_cast<const unsigned*>(sm + o_ + 16); \
      WL##nt##_0 = *reinterpret_cast<const unsigned*>(sm + o_ + 10240); \
      WL##nt##_1 = *reinterpret_cast<const unsigned*>(sm + o_ + 10256); }

#define DOMMA_P(P, mt, nt) \
    MMAS(P##mt##nt##_0, P##mt##nt##_1, P##mt##nt##_2, P##mt##nt##_3, \
         AH##mt##_0, AH##mt##_1, AH##mt##_2, AH##mt##_3, WH##nt##_0, WH##nt##_1); \
    MMAS(P##mt##nt##_0, P##mt##nt##_1, P##mt##nt##_2, P##mt##nt##_3, \
         AH##mt##_0, AH##mt##_1, AH##mt##_2, AH##mt##_3, WL##nt##_0, WL##nt##_1); \
    MMAS(P##mt##nt##_0, P##mt##nt##_1, P##mt##nt##_2, P##mt##nt##_3, \
         AL##mt##_0, AL##mt##_1, AL##mt##_2, AL##mt##_3, WH##nt##_0, WH##nt##_1)

#define DEC_KS_P(P, kb_) { \
    unsigned kb = (kb_); \
    LDA(0) LDA(1) LDW(0) LDW(1) LDW(2) LDW(3) \
    DOMMA_P(P, 0, 0); DOMMA_P(P, 0, 1); DOMMA_P(P, 0, 2); DOMMA_P(P, 0, 3); \
    DOMMA_P(P, 1, 0); DOMMA_P(P, 1, 1); DOMMA_P(P, 1, 2); DOMMA_P(P, 1, 3); }

#define DEPI_P(P, mt, nt, BIASP, OUTP, DORELU) { \
    int nc = wn * 32 + nt * 8 + 2 * r4; \
    int m = m0 + wm * 32 + mt * 16 + q4; \
    float v0 = P##mt##nt##_0 + (BIASP)[nc], v1 = P##mt##nt##_1 + (BIASP)[nc + 1]; \
    float v2 = P##mt##nt##_2 + (BIASP)[nc], v3 = P##mt##nt##_3 + (BIASP)[nc + 1]; \
    if (DORELU) { v0 = fmaxf(v0, 0.f); v1 = fmaxf(v1, 0.f); \
                  v2 = fmaxf(v2, 0.f); v3 = fmaxf(v3, 0.f); } \
    if (m < n) *reinterpret_cast<float2*>(&(OUTP)[(size_t)m * F + nc]) = make_float2(v0, v1); \
    if (m + 8 < n) *reinterpret_cast<float2*>(&(OUTP)[(size_t)(m + 8) * F + nc]) = make_float2(v2, v3); }

// dx-phase: warp wn==ck applies bias to its h accs, writes h to global AND
// split-packs into A smem planes (chunk-local col = nt*8+2r4).
#define HWR(mt, nt) { \
    int ncl = nt * 16 + r4 * 4; \
    int ncg = wn * 32 + nt * 8 + 2 * r4; \
    int ml0 = wm * 32 + mt * 16 + q4; \
    float v0 = C##mt##nt##_0 + bias[ncg], v1 = C##mt##nt##_1 + bias[ncg + 1]; \
    float v2 = C##mt##nt##_2 + bias[ncg], v3 = C##mt##nt##_3 + bias[ncg + 1]; \
    unsigned hp_, lp_; \
    SPLITPACK(v0, v1, hp_, lp_); \
    *reinterpret_cast<unsigned*>(sm + ml0 * 80 + ncl) = hp_; \
    *reinterpret_cast<unsigned*>(sm + 5120 + ml0 * 80 + ncl) = lp_; \
    if (m0 + ml0 < n) \
        *reinterpret_cast<float2*>(&out[(size_t)(m0 + ml0) * F + ncg]) = make_float2(v0, v1); \
    SPLITPACK(v2, v3, hp_, lp_); \
    *reinterpret_cast<unsigned*>(sm + (ml0 + 8) * 80 + ncl) = hp_; \
    *reinterpret_cast<unsigned*>(sm + 5120 + (ml0 + 8) * 80 + ncl) = lp_; \
    if (m0 + ml0 + 8 < n) \
        *reinterpret_cast<float2*>(&out[(size_t)(m0 + ml0 + 8) * F + ncg]) = make_float2(v2, v3); }

// CFG 1: g_h1 = relu(agg(x)@w1l^T + b1l + x@w1r^T)                [weights 0,1]
// CFG 2: outp = agg(g_h1)@w2l^T + b2l + g_h1@w2r^T; out2 = h@wdec^T+b [w 2,3,4]
// Aggregation for rows m0..m0+63 is computed IN-BLOCK (warp w -> nodes m0+8w..+7,
// lane = float4 column), staged through g_agg (block-private rows, L2-hot).
template <int CFG>
__global__ void __launch_bounds__(256)
layer_mma(const float* __restrict__ a2p, const float* __restrict__ bias,
          float* __restrict__ outp, const float* __restrict__ bias2,
          float* __restrict__ out2, int n) {
    __shared__ __align__(16) char sm[30720];

    const int NCHUNK = 8;
    float* out = (CFG == 1) ? (float*)g_h1 : outp;

    int tid = threadIdx.x, lane = tid & 31, wid = tid >> 5;
    int wm = wid & 1, wn = wid >> 1;           // 2 m-warps x 4 n-warps
    int q4 = lane >> 2, r4 = lane & 3;
    int m0 = blockIdx.x * 64;

    // ---- in-block aggregation prologue (bitwise-identical to agg_kernel) ----
    {
        const float* asrc = (CFG == 1) ? a2p : (const float*)g_h1;
        const float4* in4 = reinterpret_cast<const float4*>(asrc);
#pragma unroll
        for (int i = 0; i < 8; i++) {
            int node = m0 + wid * 8 + i;
            if (node < n) {
                int beg = g_off[node], end = g_off[node + 1];
                float x0 = 0.f, x1 = 0.f, x2 = 0.f, x3 = 0.f;
                int e = beg;
                for (; e + 4 <= end; e += 4) {
                    int s0 = g_srcs[e], s1 = g_srcs[e + 1], s2 = g_srcs[e + 2], s3 = g_srcs[e + 3];
                    float4 v0 = in4[(size_t)s0 * 32 + lane];
                    float4 v1 = in4[(size_t)s1 * 32 + lane];
                    float4 v2 = in4[(size_t)s2 * 32 + lane];
                    float4 v3 = in4[(size_t)s3 * 32 + lane];
                    x0 += v0.x + v1.x + v2.x + v3.x;
                    x1 += v0.y + v1.y + v2.y + v3.y;
                    x2 += v0.z + v1.z + v2.z + v3.z;
                    x3 += v0.w + v1.w + v2.w + v3.w;
                }
                for (; e < end; e++) {
                    int s = g_srcs[e];
                    float4 v = in4[(size_t)s * 32 + lane];
                    x0 += v.x; x1 += v.y; x2 += v.z; x3 += v.w;
                }
                int d = end - beg;
                float inv = (d > 0) ? (1.0f / (float)d) : 0.0f;
                float4 r; r.x = x0 * inv; r.y = x1 * inv; r.z = x2 * inv; r.w = x3 * inv;
                reinterpret_cast<float4*>(g_agg)[(size_t)node * 32 + lane] = r;
            }
        }
    }
    __syncthreads();   // agg rows visible block-wide before pass-0 loads

    DACC_P(C, 0, 0); DACC_P(C, 0, 1); DACC_P(C, 0, 2); DACC_P(C, 0, 3);
    DACC_P(C, 1, 0); DACC_P(C, 1, 1); DACC_P(C, 1, 2); DACC_P(C, 1, 3);

    unsigned aBase = (unsigned)((wm * 32 + q4) * 80 + r4 * 4);
    unsigned wBase = (unsigned)(10240 + (wn * 32 + q4) * 80 + r4 * 4);

    // loader coordinates (fixed per thread)
    int fA0 = tid * 2, fA1 = tid * 2 + 1;
    int rA0 = fA0 >> 3, jA0 = fA0 & 7;
    int rA1 = fA1 >> 3, jA1 = fA1 & 7;
    int rWa = tid >> 2, qWa = tid & 3;         // uint4 coords: rows tid>>2 and +64
    float4 PA0, PA1;
    uint4  PW0, PW1, PW2, PW3;

#define PRELOAD(cc_) { \
        int p_ = (cc_) >> 2, ck_ = (cc_) & 3; \
        const float* ap_; \
        if (p_ == 0)       ap_ = (const float*)g_agg; \
        else if (CFG == 1) ap_ = a2p; \
        else               ap_ = (const float*)g_h1; \
        int wi_ = (CFG == 1) ? p_ : 2 + p_; \
        const float4* a4_ = reinterpret_cast<const float4*>(ap_); \
        const uint4* wh4_ = reinterpret_cast<const uint4*>(g_wpkh) + (size_t)(wi_ * 4 + ck_) * 512; \
        const uint4* wl4_ = reinterpret_cast<const uint4*>(g_wpkl) + (size_t)(wi_ * 4 + ck_) * 512; \
        PA0 = (m0 + rA0 < n) ? a4_[(size_t)(m0 + rA0) * 32 + ck_ * 8 + jA0] \
                             : make_float4(0.f, 0.f, 0.f, 0.f); \
        PA1 = (m0 + rA1 < n) ? a4_[(size_t)(m0 + rA1) * 32 + ck_ * 8 + jA1] \
                             : make_float4(0.f, 0.f, 0.f, 0.f); \
        PW0 = wh4_[tid]; \
        PW1 = wh4_[tid + 256]; \
        PW2 = wl4_[tid]; \
        PW3 = wl4_[tid + 256]; }

    PRELOAD(0)
    for (int cc = 0; cc < NCHUNK; cc++) {
        __syncthreads();
        {
            unsigned hp0, lp0, hp1, lp1;
            SPLITPACK(PA0.x, PA0.y, hp0, lp0); SPLITPACK(PA0.z, PA0.w, hp1, lp1);
            *reinterpret_cast<uint2*>(sm + rA0 * 80 + jA0 * 8) = make_uint2(hp0, hp1);
            *reinterpret_cast<uint2*>(sm + 5120 + rA0 * 80 + jA0 * 8) = make_uint2(lp0, lp1);
            SPLITPACK(PA1.x, PA1.y, hp0, lp0); SPLITPACK(PA1.z, PA1.w, hp1, lp1);
            *reinterpret_cast<uint2*>(sm + rA1 * 80 + jA1 * 8) = make_uint2(hp0, hp1);
            *reinterpret_cast<uint2*>(sm + 5120 + rA1 * 80 + jA1 * 8) = make_uint2(lp0, lp1);
            *reinterpret_cast<uint4*>(sm + 10240 + rWa * 80 + qWa * 16) = PW0;
            *reinterpret_cast<uint4*>(sm + 10240 + (rWa + 64) * 80 + qWa * 16) = PW1;
            *reinterpret_cast<uint4*>(sm + 20480 + rWa * 80 + qWa * 16) = PW2;
            *reinterpret_cast<uint4*>(sm + 20480 + (rWa + 64) * 80 + qWa * 16) = PW3;
        }
        __syncthreads();
        if (cc + 1 < NCHUNK) PRELOAD(cc + 1)
        DEC_KS_P(C, 0u)
        DEC_KS_P(C, 32u)
    }
#undef PRELOAD

    if (CFG == 1) {
        DEPI_P(C, 0, 0, bias, out, true) DEPI_P(C, 0, 1, bias, out, true)
        DEPI_P(C, 0, 2, bias, out, true) DEPI_P(C, 0, 3, bias, out, true)
        DEPI_P(C, 1, 0, bias, out, true) DEPI_P(C, 1, 1, bias, out, true)
        DEPI_P(C, 1, 2, bias, out, true) DEPI_P(C, 1, 3, bias, out, true)
    } else {
        // ---- fused decoder: dx = h@wdec^T + bdec ----
        DACC_P(D, 0, 0); DACC_P(D, 0, 1); DACC_P(D, 0, 2); DACC_P(D, 0, 3);
        DACC_P(D, 1, 0); DACC_P(D, 1, 1); DACC_P(D, 1, 2); DACC_P(D, 1, 3);
        for (int ck = 0; ck < 4; ck++) {
            __syncthreads();                   // prior chunk's MMA reads done
            if (wn == ck) {
                HWR(0, 0) HWR(0, 1) HWR(0, 2) HWR(0, 3)
                HWR(1, 0) HWR(1, 1) HWR(1, 2) HWR(1, 3)
            }
            {   // wdec chunk planes -> smem (weight index 4)
                const uint4* wh4_ = reinterpret_cast<const uint4*>(g_wpkh) + (size_t)(16 + ck) * 512;
                const uint4* wl4_ = reinterpret_cast<const uint4*>(g_wpkl) + (size_t)(16 + ck) * 512;
                *reinterpret_cast<uint4*>(sm + 10240 + rWa * 80 + qWa * 16) = wh4_[tid];
                *reinterpret_cast<uint4*>(sm + 10240 + (rWa + 64) * 80 + qWa * 16) = wh4_[tid + 256];
                *reinterpret_cast<uint4*>(sm + 20480 + rWa * 80 + qWa * 16) = wl4_[tid];
                *reinterpret_cast<uint4*>(sm + 20480 + (rWa + 64) * 80 + qWa * 16) = wl4_[tid + 256];
            }
            __syncthreads();
            DEC_KS_P(D, 0u)
            DEC_KS_P(D, 32u)
        }
        DEPI_P(D, 0, 0, bias2, out2, false) DEPI_P(D, 0, 1, bias2, out2, false)
        DEPI_P(D, 0, 2, bias2, out2, false) DEPI_P(D, 0, 3, bias2, out2, false)
        DEPI_P(D, 1, 0, bias2, out2, false) DEPI_P(D, 1, 1, bias2, out2, false)
        DEPI_P(D, 1, 2, bias2, out2, false) DEPI_P(D, 1, 3, bias2, out2, false)
    }
}

// ---------------- launch ------------------------------------------------------
extern "C" void kernel_launch(void* const* d_in, const int* in_sizes, int n_in,
                              void* d_out, int out_size) {
    const float* x     = (const float*)d_in[0];
    const int*   xedge = (const int*)d_in[1];      // int32 [2, E]
    const float* w1l   = (const float*)d_in[2];
    const float* b1l   = (const float*)d_in[3];
    const float* w1r   = (const float*)d_in[4];
    const float* w2l   = (const float*)d_in[5];
    const float* b2l   = (const float*)d_in[6];
    const float* w2r   = (const float*)d_in[7];
    const float* wdec  = (const float*)d_in[8];
    const float* bdec  = (const float*)d_in[9];

    float* out_h  = (float*)d_out;
    float* out_dx = out_h + (size_t)N_NODES * F;

    const int mma_blocks = (N_NODES + 63) / 64;        // 1563

    // prep (zero deg + pack weights) then CSR build
    prep_kernel<<<ZERO_BLOCKS + 80, 256>>>(w1l, w1r, w2l, w2r, wdec);
    hist_kernel<<<(N_EDGES + 255) / 256, 256>>>(xedge);
    scan1_kernel<<<NB_SCAN, SCAN_B>>>();
    scan2_kernel<<<1, 256>>>();
    scan3_kernel<<<NB_SCAN, SCAN_B>>>();
    fill_kernel<<<(N_EDGES + 255) / 256, 256>>>(xedge);

    // Layer 1 (agg fused in-block): g_h1 = relu(agg(x)@w1l^T + b1l + x@w1r^T)
    layer_mma<1><<<mma_blocks, 256>>>(x, b1l, nullptr, nullptr, nullptr, N_NODES);

    // Layer 2 + decoder (agg + dec fused): out_h = agg(h1)@w2l^T + b2l + h1@w2r^T;
    //                                      out_dx = out_h@wdec^T + bdec
    layer_mma<2><<<mma_blocks, 256>>>(nullptr, b2l, out_h, bdec, out_dx, N_NODES);
}